// round 1
// baseline (speedup 1.0000x reference)
#include <cuda_runtime.h>

// Problem constants
#define BATCH   2
#define T_SEQ   2048
#define DMODEL  1024
#define NHEAD   16
#define HD      64
#define FFDIM   4096
#define BT      (BATCH*T_SEQ)          // 4096 rows

// ---------------------------------------------------------------------------
// Scratch (static __device__ globals; no allocation anywhere)
// ---------------------------------------------------------------------------
__device__ float g_Wqkv[(size_t)DMODEL * 3 * DMODEL];                 // 1024 x 3072
__device__ float g_qkv[(size_t)BT * 3 * DMODEL];                      // 4096 x 3072
__device__ float g_scores[(size_t)BATCH * NHEAD * T_SEQ * T_SEQ];     // 32 x 2048 x 2048
__device__ float g_obuf[(size_t)BT * DMODEL];
__device__ float g_proj[(size_t)BT * DMODEL];
__device__ float g_out1[(size_t)BT * DMODEL];
__device__ float g_h1[(size_t)BT * FFDIM];
__device__ float g_ff[(size_t)BT * DMODEL];

// ---------------------------------------------------------------------------
// Pack Wq|Wk|Wv (each H x D x 64, h-major) into Wqkv[d][n], n = which*1024 + h*64 + k
// ---------------------------------------------------------------------------
__global__ void pack_w_kernel(const float* __restrict__ Wq,
                              const float* __restrict__ Wk,
                              const float* __restrict__ Wv,
                              float* __restrict__ Wqkv) {
    int idx = blockIdx.x * blockDim.x + threadIdx.x;   // over 1024*3072
    int d = idx / (3 * DMODEL);
    int n = idx % (3 * DMODEL);
    const float* W = (n < DMODEL) ? Wq : ((n < 2 * DMODEL) ? Wk : Wv);
    int nn = n & (DMODEL - 1);
    int h = nn >> 6;
    int k = nn & 63;
    Wqkv[idx] = W[((size_t)h * DMODEL + d) * HD + k];
}

// ---------------------------------------------------------------------------
// Generic tiled SGEMM.
// C[M,N] = alpha * A[M,K] x B  (+bias) (+relu)
//   TRANSB=false: B is K x N row-major (ldb)
//   TRANSB=true : B is N x K row-major (ldb)  (i.e. C = alpha * A * B^T)
// Batched via blockIdx.z: z1 = z / zInner, z2 = z % zInner;
//   each operand offset by z1*s?1 + z2*s?2 (element strides).
// All of M,N multiples of BM,BN; K multiple of BK; pointers float4-aligned.
// ---------------------------------------------------------------------------
template<int BM, int BN, int BK, int TM, int TN, bool TRANSB, bool RELU, bool HASBIAS>
__global__ void __launch_bounds__((BM/TM)*(BN/TN))
sgemm_kernel(const float* __restrict__ Ag, const float* __restrict__ Bg,
             float* __restrict__ Cg, const float* __restrict__ bias,
             int M, int N, int K, int lda, int ldb, int ldc,
             long long sA1, long long sA2,
             long long sB1, long long sB2,
             long long sC1, long long sC2,
             int zInner, float alpha)
{
    constexpr int NTH = (BM/TM)*(BN/TN);
    const int z1 = blockIdx.z / zInner;
    const int z2 = blockIdx.z % zInner;
    const float* A = Ag + z1 * sA1 + z2 * sA2;
    const float* B = Bg + z1 * sB1 + z2 * sB2;
    float*       C = Cg + z1 * sC1 + z2 * sC2;

    __shared__ __align__(16) float As[BK][BM + 4];
    __shared__ __align__(16) float Bs[BK][BN + 4];

    const int tid  = threadIdx.x;
    const int row0 = blockIdx.y * BM;
    const int col0 = blockIdx.x * BN;
    const int tcol = tid % (BN/TN);
    const int trow = tid / (BN/TN);

    float acc[TM][TN];
    #pragma unroll
    for (int i = 0; i < TM; i++)
        #pragma unroll
        for (int j = 0; j < TN; j++) acc[i][j] = 0.f;

    for (int k0 = 0; k0 < K; k0 += BK) {
        // load A tile (BM x BK), store transposed into As[k][m]
        #pragma unroll
        for (int i = tid; i < BM * (BK/4); i += NTH) {
            int r  = i / (BK/4);
            int c4 = (i % (BK/4)) * 4;
            float4 v = *reinterpret_cast<const float4*>(
                A + (size_t)(row0 + r) * lda + k0 + c4);
            As[c4+0][r] = v.x; As[c4+1][r] = v.y;
            As[c4+2][r] = v.z; As[c4+3][r] = v.w;
        }
        if (TRANSB) {
            // B is N x K: load BN x BK, store transposed into Bs[k][n]
            #pragma unroll
            for (int i = tid; i < BN * (BK/4); i += NTH) {
                int r  = i / (BK/4);
                int c4 = (i % (BK/4)) * 4;
                float4 v = *reinterpret_cast<const float4*>(
                    B + (size_t)(col0 + r) * ldb + k0 + c4);
                Bs[c4+0][r] = v.x; Bs[c4+1][r] = v.y;
                Bs[c4+2][r] = v.z; Bs[c4+3][r] = v.w;
            }
        } else {
            // B is K x N: load BK x BN directly
            #pragma unroll
            for (int i = tid; i < BK * (BN/4); i += NTH) {
                int r  = i / (BN/4);
                int c4 = (i % (BN/4)) * 4;
                float4 v = *reinterpret_cast<const float4*>(
                    B + (size_t)(k0 + r) * ldb + col0 + c4);
                *reinterpret_cast<float4*>(&Bs[r][c4]) = v;
            }
        }
        __syncthreads();

        #pragma unroll
        for (int kk = 0; kk < BK; kk++) {
            float ra[TM], rb[TN];
            #pragma unroll
            for (int i = 0; i < TM; i += 4) {
                float4 t = *reinterpret_cast<const float4*>(&As[kk][trow*TM + i]);
                ra[i+0] = t.x; ra[i+1] = t.y; ra[i+2] = t.z; ra[i+3] = t.w;
            }
            #pragma unroll
            for (int j = 0; j < TN; j += 4) {
                float4 t = *reinterpret_cast<const float4*>(&Bs[kk][tcol*TN + j]);
                rb[j+0] = t.x; rb[j+1] = t.y; rb[j+2] = t.z; rb[j+3] = t.w;
            }
            #pragma unroll
            for (int i = 0; i < TM; i++)
                #pragma unroll
                for (int j = 0; j < TN; j++)
                    acc[i][j] = fmaf(ra[i], rb[j], acc[i][j]);
        }
        __syncthreads();
    }

    // epilogue
    #pragma unroll
    for (int i = 0; i < TM; i++) {
        size_t r = (size_t)(row0 + trow * TM + i);
        #pragma unroll
        for (int j = 0; j < TN; j += 4) {
            int c = col0 + tcol * TN + j;
            float4 v;
            v.x = acc[i][j+0] * alpha;
            v.y = acc[i][j+1] * alpha;
            v.z = acc[i][j+2] * alpha;
            v.w = acc[i][j+3] * alpha;
            if (HASBIAS) {
                float4 bb = *reinterpret_cast<const float4*>(bias + c);
                v.x += bb.x; v.y += bb.y; v.z += bb.z; v.w += bb.w;
            }
            if (RELU) {
                v.x = fmaxf(v.x, 0.f); v.y = fmaxf(v.y, 0.f);
                v.z = fmaxf(v.z, 0.f); v.w = fmaxf(v.w, 0.f);
            }
            *reinterpret_cast<float4*>(C + r * ldc + c) = v;
        }
    }
}

// ---------------------------------------------------------------------------
// Column softmax over the QUERY axis: scores[bh][q][s] normalized over q.
// One thread per column s; strided reads are coalesced across threads.
// ---------------------------------------------------------------------------
__global__ void softmax_q_kernel(float* __restrict__ sc) {
    int s = blockIdx.x * blockDim.x + threadIdx.x;          // column
    float* base = sc + (size_t)blockIdx.y * T_SEQ * T_SEQ + s;
    float m = -1e30f, sum = 0.f;
    for (int q = 0; q < T_SEQ; q++) {
        float x  = base[(size_t)q * T_SEQ];
        float mn = fmaxf(m, x);
        sum = sum * __expf(m - mn) + __expf(x - mn);
        m = mn;
    }
    float r = 1.f / sum;
    for (int q = 0; q < T_SEQ; q++) {
        float x = base[(size_t)q * T_SEQ];
        base[(size_t)q * T_SEQ] = __expf(x - m) * r;
    }
}

// ---------------------------------------------------------------------------
// out = meanstd_norm(A + B), per row of DMODEL, ddof=1 (÷1023), no eps.
// One block (256 threads) per row.
// ---------------------------------------------------------------------------
__device__ __forceinline__ float block_reduce_sum(float v, float* sh) {
    int lane = threadIdx.x & 31, warp = threadIdx.x >> 5;
    #pragma unroll
    for (int o = 16; o; o >>= 1) v += __shfl_xor_sync(0xffffffffu, v, o);
    if (lane == 0) sh[warp] = v;
    __syncthreads();
    if (warp == 0) {
        v = (lane < 8) ? sh[lane] : 0.f;
        #pragma unroll
        for (int o = 16; o; o >>= 1) v += __shfl_xor_sync(0xffffffffu, v, o);
        if (lane == 0) sh[0] = v;
    }
    __syncthreads();
    float r = sh[0];
    __syncthreads();            // allow sh reuse
    return r;
}

__global__ void add_norm_kernel(const float* __restrict__ A,
                                const float* __restrict__ B,
                                float* __restrict__ out) {
    __shared__ float sh[32];
    size_t row = blockIdx.x;
    const float* pa = A + row * DMODEL;
    const float* pb = B + row * DMODEL;
    float* po = out + row * DMODEL;

    float v[4];
    float s = 0.f;
    #pragma unroll
    for (int i = 0; i < 4; i++) {
        int c = threadIdx.x + i * 256;
        v[i] = pa[c] + pb[c];
        s += v[i];
    }
    float total = block_reduce_sum(s, sh);
    float mean = total * (1.f / (float)DMODEL);

    float ss = 0.f;
    #pragma unroll
    for (int i = 0; i < 4; i++) {
        float d = v[i] - mean;
        ss += d * d;
    }
    float tss = block_reduce_sum(ss, sh);
    float rstd = rsqrtf(tss * (1.f / (float)(DMODEL - 1)));

    #pragma unroll
    for (int i = 0; i < 4; i++) {
        int c = threadIdx.x + i * 256;
        po[c] = (v[i] - mean) * rstd;
    }
}

// ---------------------------------------------------------------------------
// Launch
// ---------------------------------------------------------------------------
extern "C" void kernel_launch(void* const* d_in, const int* in_sizes, int n_in,
                              void* d_out, int out_size) {
    const float* x  = (const float*)d_in[0];
    const float* Wq = (const float*)d_in[1];
    const float* Wk = (const float*)d_in[2];
    const float* Wv = (const float*)d_in[3];
    const float* Wo = (const float*)d_in[4];
    const float* W1 = (const float*)d_in[5];
    const float* b1 = (const float*)d_in[6];
    const float* W2 = (const float*)d_in[7];
    const float* b2 = (const float*)d_in[8];
    float* out = (float*)d_out;

    float *Wqkv, *qkv, *scores, *obuf, *proj, *out1, *h1, *ff;
    cudaGetSymbolAddress((void**)&Wqkv,   g_Wqkv);
    cudaGetSymbolAddress((void**)&qkv,    g_qkv);
    cudaGetSymbolAddress((void**)&scores, g_scores);
    cudaGetSymbolAddress((void**)&obuf,   g_obuf);
    cudaGetSymbolAddress((void**)&proj,   g_proj);
    cudaGetSymbolAddress((void**)&out1,   g_out1);
    cudaGetSymbolAddress((void**)&h1,     g_h1);
    cudaGetSymbolAddress((void**)&ff,     g_ff);

    const long long TT = (long long)T_SEQ * T_SEQ;

    // 1) pack Wq|Wk|Wv -> Wqkv (1024 x 3072)
    pack_w_kernel<<<(DMODEL * 3 * DMODEL) / 256, 256>>>(Wq, Wk, Wv, Wqkv);

    // 2) QKV = X(4096x1024) @ Wqkv(1024x3072)
    sgemm_kernel<128,128,16,8,8,false,false,false>
        <<<dim3(3*DMODEL/128, BT/128, 1), 256>>>(
            x, Wqkv, qkv, nullptr,
            BT, 3*DMODEL, DMODEL, DMODEL, 3*DMODEL, 3*DMODEL,
            0,0, 0,0, 0,0, 1, 1.0f);

    // 3) scores[b,h] = (Q @ K^T) / 8 ; batched over z=(b,h), zInner=NHEAD
    sgemm_kernel<128,128,16,8,8,true,false,false>
        <<<dim3(T_SEQ/128, T_SEQ/128, BATCH*NHEAD), 256>>>(
            qkv /*Q*/, qkv + DMODEL /*K*/, scores, nullptr,
            T_SEQ, T_SEQ, HD, 3*DMODEL, 3*DMODEL, T_SEQ,
            (long long)T_SEQ*3*DMODEL, HD,
            (long long)T_SEQ*3*DMODEL, HD,
            (long long)NHEAD*TT, TT,
            NHEAD, 0.125f);

    // 4) softmax over query axis (columns)
    softmax_q_kernel<<<dim3(T_SEQ/256, BATCH*NHEAD), 256>>>(scores);

    // 5) O[b,h] = attn(2048x2048) @ V(2048x64) -> obuf[b,t,h*64+v]
    sgemm_kernel<128,64,16,8,4,false,false,false>
        <<<dim3(1, T_SEQ/128, BATCH*NHEAD), 256>>>(
            scores, qkv + 2*DMODEL /*V*/, obuf, nullptr,
            T_SEQ, HD, T_SEQ, T_SEQ, 3*DMODEL, DMODEL,
            (long long)NHEAD*TT, TT,
            (long long)T_SEQ*3*DMODEL, HD,
            (long long)T_SEQ*DMODEL, HD,
            NHEAD, 1.0f);

    // 6) proj = obuf(4096x1024) @ Wo(1024x1024)
    sgemm_kernel<128,128,16,8,8,false,false,false>
        <<<dim3(DMODEL/128, BT/128, 1), 256>>>(
            obuf, Wo, proj, nullptr,
            BT, DMODEL, DMODEL, DMODEL, DMODEL, DMODEL,
            0,0, 0,0, 0,0, 1, 1.0f);

    // 7) out1 = norm(proj + x)
    add_norm_kernel<<<BT, 256>>>(proj, x, out1);

    // 8) h1 = relu(out1 @ W1 + b1)   (4096x4096)
    sgemm_kernel<128,128,16,8,8,false,true,true>
        <<<dim3(FFDIM/128, BT/128, 1), 256>>>(
            out1, W1, h1, b1,
            BT, FFDIM, DMODEL, DMODEL, FFDIM, FFDIM,
            0,0, 0,0, 0,0, 1, 1.0f);

    // 9) ff = h1 @ W2 + b2           (4096x1024)
    sgemm_kernel<128,128,16,8,8,false,false,true>
        <<<dim3(DMODEL/128, BT/128, 1), 256>>>(
            h1, W2, ff, b2,
            BT, DMODEL, FFDIM, FFDIM, DMODEL, DMODEL,
            0,0, 0,0, 0,0, 1, 1.0f);

    // 10) out = norm(ff + out1)
    add_norm_kernel<<<BT, 256>>>(ff, out1, out);
}